// round 11
// baseline (speedup 1.0000x reference)
#include <cuda_runtime.h>
#include <cuda_bf16.h>
#include <cstdint>

// Problem shape (fixed by setup_inputs): preds [T,B,C] f32, targets [B,L] i64.
#define TT 128
#define BB 128
#define CC 8192
#define LL 50
#define NSLOT 51   // slot 0 = blank, slots 1..50 = labels

// Dense accumulator: g_acc[b][slot] = sum_t exp(x[t,b,c_slot])/Z[t,b].
// Zero at module load; finish_kernel re-zeroes after reading -> invariant
// holds across graph replays. 26 KB, L2-resident.
__device__ float g_acc[BB * NSLOT];

// Fast exp on the FMA pipe (no MUFU). Rel err ~5e-5.
__device__ __forceinline__ float fast_exp(float x) {
    const float L2E = 1.4426950408889634f;
    float t  = fmaf(x, L2E, 12582912.0f);
    float nf = t - 12582912.0f;
    float f  = fmaf(x, L2E, -nf);
    int   ni = __float_as_int(t) - 0x4B400000;
    float sc = __int_as_float((ni << 23) + 0x3F800000);
    float p = fmaf(f, 0.009618129f, 0.05550411f);
    p = fmaf(f, p, 0.2402265f);
    p = fmaf(f, p, 0.6931472f);
    float fp = f * p;
    return fmaf(fp, sc, sc);
}

// Fast natural log on the FMA pipe (no MUFU). Exponent extraction with the
// [2/3, 4/3) reduction + degree-5 log1p poly. Abs err ~1e-5.
__device__ __forceinline__ float fast_logf(float a) {
    int   e = (__float_as_int(a) - 0x3f2aaaab) & 0xff800000;
    float m = __int_as_float(__float_as_int(a) - e);   // m in [2/3, 4/3)
    float i = (float)e * 1.19209290e-7f;               // e / 2^23
    float f = m - 1.0f;
    float s = f * f;
    float r = fmaf(0.230836749f, f, -0.279208571f);
    float t = fmaf(0.331826031f, f, -0.498910338f);
    r = fmaf(r, s, t);
    r = fmaf(r, s, f);
    return fmaf(i, 0.693147182f, r);
}

// ---------------------------------------------------------------------------
// Kernel 1: one block per (t,b) row (unchanged from R10's best stream).
//   label -> fire sparse gather early -> stream 32 KB -> Z -> REDG.
// ---------------------------------------------------------------------------
__global__ __launch_bounds__(256) void zsum_kernel(
    const float* __restrict__ preds,
    const long long* __restrict__ tgt)
{
    int tb  = blockIdx.x;                 // = t*BB + b
    int b   = tb & (BB - 1);
    int tid = threadIdx.x;

    const float* rowf = preds + (size_t)tb * CC;

    int c = 0;                            // slot 0 -> blank class 0
    if (tid >= 1 && tid < NSLOT) {
        long long l = tgt[(size_t)b * LL + (tid - 1)];
        if (l > 0 && l < CC) c = (int)l;  // invalid -> class 0 (weight 0 later)
    }
    float xc = 0.0f;
    if (tid < NSLOT) xc = __ldg(rowf + c);   // in flight during the stream

    const float4* row = reinterpret_cast<const float4*>(rowf);
    float acc = 0.0f;
#pragma unroll
    for (int i = 0; i < 8; i++) {
        float4 v = row[tid + i * 256];    // 8 front-batched LDG.128
        acc += fast_exp(v.x) + fast_exp(v.y) + fast_exp(v.z) + fast_exp(v.w);
    }
#pragma unroll
    for (int o = 16; o > 0; o >>= 1)
        acc += __shfl_xor_sync(0xFFFFFFFFu, acc, o);

    __shared__ float s[8];
    if ((tid & 31) == 0) s[tid >> 5] = acc;
    __syncthreads();

    if (tid < NSLOT) {
        float z = s[0] + s[1] + s[2] + s[3] + s[4] + s[5] + s[6] + s[7];
        atomicAdd(&g_acc[b * NSLOT + tid], fast_exp(xc) * (1.0f / z));
    }
}

// ---------------------------------------------------------------------------
// Kernel 2: ONE block, 1024 threads. All loads L2-hot (zsum just touched tgt
// and g_acc). FMA-pipe logs (one SM can't afford 6528 MUFU ops). Writes *out
// directly (no atomic, no pre-zero) and re-zeroes g_acc behind itself.
// ---------------------------------------------------------------------------
__global__ __launch_bounds__(1024) void finish_kernel(
    const long long* __restrict__ tgt,
    float* __restrict__ out)
{
    int tid = threadIdx.x;

    // Phase 1: npos[b] = # of valid positive labels per row.
    __shared__ float snpos[BB];
    if (tid < BB) snpos[tid] = 0.0f;
    __syncthreads();
    for (int i = tid; i < BB * LL; i += 1024) {       // coalesced, L2-hot
        long long l = tgt[i];
        if (l > 0 && l < CC) atomicAdd(&snpos[i / LL], 1.0f);
    }
    __syncthreads();

    // Phase 2: per-(b,slot) contributions.
    const float LOG_T = 4.852030263919617f;    // ln(128)
    float lsum = 0.0f;
    for (int idx = tid; idx < BB * NSLOT; idx += 1024) {
        int b    = idx / NSLOT;
        int slot = idx - b * NSLOT;
        float total = g_acc[idx];
        g_acc[idx] = 0.0f;                     // restore invariant
        float w;
        if (slot == 0) {
            w = (float)TT - snpos[b];
        } else {
            long long l = tgt[b * LL + slot - 1];     // L1-hot from phase 1
            w = (l > 0 && l < CC) ? 1.0f : 0.0f;
        }
        if (w != 0.0f) lsum += w * (fast_logf(total) - LOG_T);
    }

    // Phase 3: block reduce 1024 partials -> single store.
#pragma unroll
    for (int o = 16; o > 0; o >>= 1)
        lsum += __shfl_xor_sync(0xFFFFFFFFu, lsum, o);
    __shared__ float sred[32];
    if ((tid & 31) == 0) sred[tid >> 5] = lsum;
    __syncthreads();
    if (tid < 32) {
        float v = sred[tid];
#pragma unroll
        for (int o = 16; o > 0; o >>= 1)
            v += __shfl_xor_sync(0xFFFFFFFFu, v, o);
        if (tid == 0)
            *out = -v * (1.0f / ((float)BB * (float)TT));
    }
}

extern "C" void kernel_launch(void* const* d_in, const int* in_sizes, int n_in,
                              void* d_out, int out_size)
{
    const float*     preds = (const float*)d_in[0];
    const long long* tgt   = (const long long*)d_in[1];
    float*           out   = (float*)d_out;

    zsum_kernel<<<TT * BB, 256>>>(preds, tgt);
    finish_kernel<<<1, 1024>>>(tgt, out);
}

// round 12
// speedup vs baseline: 1.0464x; 1.0464x over previous
#include <cuda_runtime.h>
#include <cuda_bf16.h>
#include <cstdint>

// Problem shape (fixed by setup_inputs): preds [T,B,C] f32, targets [B,L] i64.
#define TT 128
#define BB 128
#define CC 8192
#define LL 50
#define NSLOT 51   // slot 0 = blank, slots 1..50 = labels

// Dense accumulator: g_acc[b][slot] = sum_t exp(x[t,b,c_slot])/Z[t,b].
// Zero at module load; finish_kernel re-zeroes after reading -> invariant
// holds across graph replays. 26 KB, L2-resident.
__device__ float g_acc[BB * NSLOT];

// Fast exp on the FMA pipe (no MUFU). Rel err ~5e-5.
__device__ __forceinline__ float fast_exp(float x) {
    const float L2E = 1.4426950408889634f;
    float t  = fmaf(x, L2E, 12582912.0f);
    float nf = t - 12582912.0f;
    float f  = fmaf(x, L2E, -nf);
    int   ni = __float_as_int(t) - 0x4B400000;
    float sc = __int_as_float((ni << 23) + 0x3F800000);
    float p = fmaf(f, 0.009618129f, 0.05550411f);
    p = fmaf(f, p, 0.2402265f);
    p = fmaf(f, p, 0.6931472f);
    float fp = f * p;
    return fmaf(fp, sc, sc);
}

// Fast natural log on the FMA pipe (no MUFU). Abs err ~1e-5.
__device__ __forceinline__ float fast_logf(float a) {
    int   e = (__float_as_int(a) - 0x3f2aaaab) & 0xff800000;
    float m = __int_as_float(__float_as_int(a) - e);   // m in [2/3, 4/3)
    float i = (float)e * 1.19209290e-7f;               // e / 2^23
    float f = m - 1.0f;
    float s = f * f;
    float r = fmaf(0.230836749f, f, -0.279208571f);
    float t = fmaf(0.331826031f, f, -0.498910338f);
    r = fmaf(r, s, t);
    r = fmaf(r, s, f);
    return fmaf(i, 0.693147182f, r);
}

// ---------------------------------------------------------------------------
// Kernel 1: one block per (t,b) row (exact R10 best stream: 74.3 us).
//   label -> fire sparse gather early -> stream 32 KB -> Z -> REDG.
// ---------------------------------------------------------------------------
__global__ __launch_bounds__(256) void zsum_kernel(
    const float* __restrict__ preds,
    const long long* __restrict__ tgt,
    float* __restrict__ out)
{
    int tb  = blockIdx.x;                 // = t*BB + b
    int b   = tb & (BB - 1);
    int tid = threadIdx.x;
    if (tb == 0 && tid == 0) *out = 0.0f;

    const float* rowf = preds + (size_t)tb * CC;

    int c = 0;                            // slot 0 -> blank class 0
    if (tid >= 1 && tid < NSLOT) {
        long long l = tgt[(size_t)b * LL + (tid - 1)];
        if (l > 0 && l < CC) c = (int)l;  // invalid -> class 0 (weight 0 later)
    }
    float xc = 0.0f;
    if (tid < NSLOT) xc = __ldg(rowf + c);   // in flight during the stream

    const float4* row = reinterpret_cast<const float4*>(rowf);
    float acc = 0.0f;
#pragma unroll
    for (int i = 0; i < 8; i++) {
        float4 v = row[tid + i * 256];    // 8 front-batched LDG.128
        acc += fast_exp(v.x) + fast_exp(v.y) + fast_exp(v.z) + fast_exp(v.w);
    }
#pragma unroll
    for (int o = 16; o > 0; o >>= 1)
        acc += __shfl_xor_sync(0xFFFFFFFFu, acc, o);

    __shared__ float s[8];
    if ((tid & 31) == 0) s[tid >> 5] = acc;
    __syncthreads();

    if (tid < NSLOT) {
        float z = s[0] + s[1] + s[2] + s[3] + s[4] + s[5] + s[6] + s[7];
        atomicAdd(&g_acc[b * NSLOT + tid], fast_exp(xc) * (1.0f / z));
    }
}

// ---------------------------------------------------------------------------
// Kernel 2: 8 blocks x 1024 threads; block bg owns b in [bg*16, bg*16+16).
// One slot per thread (no serial L2 rounds), FMA-pipe logs, ONE atomicAdd
// per block (8 total -- no same-address convoy). All loads L2-hot.
// ---------------------------------------------------------------------------
__global__ __launch_bounds__(1024) void finish_kernel(
    const long long* __restrict__ tgt,
    float* __restrict__ out)
{
    int bg  = blockIdx.x;                 // b-group: 16 rows
    int tid = threadIdx.x;

    __shared__ float snpos[16];
    if (tid < 16) snpos[tid] = 0.0f;
    __syncthreads();

    // Phase 1: label counts. 800 threads load one label each (coalesced).
    if (tid < 16 * LL) {
        int b_local = tid / LL;
        long long l = tgt[(size_t)(bg * 16 + b_local) * LL + (tid % LL)];
        if (l > 0 && l < CC) atomicAdd(&snpos[b_local], 1.0f);
    }
    __syncthreads();

    // Phase 2: one slot per thread (816 active).
    const float LOG_T = 4.852030263919617f;    // ln(128)
    float contrib = 0.0f;
    if (tid < 16 * NSLOT) {
        int b_local = tid / NSLOT;
        int slot    = tid - b_local * NSLOT;
        int idx     = (bg * 16 + b_local) * NSLOT + slot;
        float total = g_acc[idx];
        g_acc[idx]  = 0.0f;                    // restore invariant
        float w;
        if (slot == 0) {
            w = (float)TT - snpos[b_local];
        } else {
            long long l = tgt[(size_t)(bg * 16 + b_local) * LL + slot - 1];  // L1-hot
            w = (l > 0 && l < CC) ? 1.0f : 0.0f;
        }
        if (w != 0.0f) contrib = w * (fast_logf(total) - LOG_T);
    }

    // Phase 3: block reduce 1024 -> 1, then a single atomic per block.
#pragma unroll
    for (int o = 16; o > 0; o >>= 1)
        contrib += __shfl_xor_sync(0xFFFFFFFFu, contrib, o);
    __shared__ float sred[32];
    if ((tid & 31) == 0) sred[tid >> 5] = contrib;
    __syncthreads();
    if (tid < 32) {
        float v = sred[tid];
#pragma unroll
        for (int o = 16; o > 0; o >>= 1)
            v += __shfl_xor_sync(0xFFFFFFFFu, v, o);
        if (tid == 0)
            atomicAdd(out, -v * (1.0f / ((float)BB * (float)TT)));
    }
}

extern "C" void kernel_launch(void* const* d_in, const int* in_sizes, int n_in,
                              void* d_out, int out_size)
{
    const float*     preds = (const float*)d_in[0];
    const long long* tgt   = (const long long*)d_in[1];
    float*           out   = (float*)d_out;

    zsum_kernel<<<TT * BB, 256>>>(preds, tgt, out);
    finish_kernel<<<8, 1024>>>(tgt, out);
}